// round 8
// baseline (speedup 1.0000x reference)
#include <cuda_runtime.h>
#include <cuda_bf16.h>
#include <math.h>

// ============================================================================
// ConvLSTM (2 stacked layers, 12 timesteps) on GB300.
//   Layer0: Cin=129 (1 input + 128 hidden), hid=128
//   Layer1: Cin=140 (128 from layer0 + 12 hidden), hid=12
//   B=16, H=W=64.
// R8: kill register spills (launch_bounds(256,1) on layer0 -> ~145 regs, no
//     STL/LDL), 2x-unrolled channel loop with compile-time buffer parity,
//     incremental channel pointers, and a re-tiled layer1 (KPB=2, RPT=2,
//     TILE_H=8 -> 768 blocks) for load balance.
// ============================================================================

#define Bsz  16
#define Hd   64
#define Wd   64
#define HW   4096
#define LSEQ 12

#define HID0 128
#define CIN0 129   // 1 + HID0
#define HID1 12
#define CIN1 140   // HID0 + HID1

#define SCOLS  66          // 64 + 2

typedef unsigned long long u64t;

// ---------------- per-layer tiling config ------------------------------------
template<int LAYER> struct Cfg;
template<> struct Cfg<0> {
    static constexpr int HIDN = 128, CIN = 129;
    static constexpr int KPB = 4, RPT = 4, TILEH = 16;
    static constexpr int SROWS = TILEH + 2;          // 18
    static constexpr int NTILE = SROWS * SCOLS;      // 1188
    static constexpr int FILLIT = (NTILE + 255) / 256; // 5
    static constexpr int MINB = 1;                   // no reg cap -> no spills
};
template<> struct Cfg<1> {
    static constexpr int HIDN = 12, CIN = 140;
    static constexpr int KPB = 2, RPT = 2, TILEH = 8;
    static constexpr int SROWS = TILEH + 2;          // 10
    static constexpr int NTILE = SROWS * SCOLS;      // 660
    static constexpr int FILLIT = (NTILE + 255) / 256; // 3
    static constexpr int MINB = 2;
};

// ---------------- persistent device state (no runtime allocation) ----------
__device__ __align__(16) float g_h0[2][Bsz*HID0*HW];   // ping-pong hidden, layer0
__device__ __align__(16) float g_c0[Bsz*HID0*HW];
__device__ __align__(16) float g_h1[2][Bsz*HID1*HW];
__device__ __align__(16) float g_c1[Bsz*HID1*HW];
__device__ float4 g_wp0[HID0*CIN0*9];   // [k][c][tap] -> (wi,wf,wo,wg)
__device__ float4 g_bp0[HID0];
__device__ float4 g_wp1[HID1*CIN1*9];
__device__ float4 g_bp1[HID1];

// ---------------- packed f32x2 helpers --------------------------------------
__device__ __forceinline__ u64t pack2(float a, float b) {
    u64t r;
    asm("mov.b64 %0, {%1, %2};" : "=l"(r) : "f"(a), "f"(b));
    return r;
}
// In-place accumulate: tied "+l" constraint -> no destination copy.
__device__ __forceinline__ void fma2ip(u64t& acc, u64t a, u64t b) {
    asm("fma.rn.f32x2 %0, %1, %2, %0;" : "+l"(acc) : "l"(a), "l"(b));
}
__device__ __forceinline__ void unpack2(u64t v, float& lo, float& hi) {
    asm("mov.b64 {%0, %1}, %2;" : "=f"(lo), "=f"(hi) : "l"(v));
}

__device__ __forceinline__ float sigf(float x) { return 1.0f / (1.0f + expf(-x)); }

// ---------------- weight/bias permutation -----------------------------------
// W layout in: [gate*HID + k][c][kh][kw]  ->  out: [k][c][tap] float4(gates)
template<int LAYER>
__global__ void prep_w(const float* __restrict__ W, const float* __restrict__ bias) {
    constexpr int HIDN = Cfg<LAYER>::HIDN;
    constexpr int CIN  = Cfg<LAYER>::CIN;
    float4* wp = (LAYER == 0) ? g_wp0 : g_wp1;
    float4* bp = (LAYER == 0) ? g_bp0 : g_bp1;

    int i = blockIdx.x * blockDim.x + threadIdx.x;
    if (i < HIDN * CIN * 9) {
        int tap = i % 9;
        int c   = (i / 9) % CIN;
        int k   = i / (9 * CIN);
        float4 v;
        v.x = W[((0 * HIDN + k) * CIN + c) * 9 + tap];   // i gate
        v.y = W[((1 * HIDN + k) * CIN + c) * 9 + tap];   // f gate
        v.z = W[((2 * HIDN + k) * CIN + c) * 9 + tap];   // o gate
        v.w = W[((3 * HIDN + k) * CIN + c) * 9 + tap];   // g gate
        wp[i] = v;
    }
    if (i < HIDN) {
        bp[i] = make_float4(bias[0 * HIDN + i], bias[1 * HIDN + i],
                            bias[2 * HIDN + i], bias[3 * HIDN + i]);
    }
}

// ---------------- state zeroing (every launch: deterministic replays) -------
__global__ void zero_state() {
    int i = blockIdx.x * blockDim.x + threadIdx.x;
    float4 z = make_float4(0.f, 0.f, 0.f, 0.f);
    if (i < (Bsz * HID0 * HW) / 4) {
        reinterpret_cast<float4*>(g_h0[0])[i] = z;
        reinterpret_cast<float4*>(g_c0)[i]    = z;
    }
    if (i < (Bsz * HID1 * HW) / 4) {
        reinterpret_cast<float4*>(g_h1[0])[i] = z;
        reinterpret_cast<float4*>(g_c1)[i]    = z;
    }
}

// ---------------- fused conv + LSTM gate step --------------------------------
// grid: (Hd/TILEH y-tiles, HIDN/KPB, B), block: 256 threads.
// Each thread: one x-column, RPT consecutive rows, KPB output channels.
// Activation tiles: duplicated-lane float2 in smem -> one LDS.64 = packed op.
template<int LAYER>
__global__ __launch_bounds__(256, Cfg<LAYER>::MINB)
void conv_step(const float* __restrict__ history, int t, int p) {
    using C = Cfg<LAYER>;
    constexpr int HIDN = C::HIDN;
    constexpr int CIN  = C::CIN;
    constexpr int KPB  = C::KPB;
    constexpr int RPT  = C::RPT;
    constexpr int FILLIT = C::FILLIT;
    constexpr int NTILE  = C::NTILE;

    const float4* __restrict__ wp;
    const float4* __restrict__ bp;
    float* cst;
    float* hout;
    const float* ch0;     // pointer to channel 0 for this batch
    const float* nx;      // pointer to next fill channel (starts at channel 1)
    const int b = blockIdx.z;

    if (LAYER == 0) {
        wp = g_wp0; bp = g_bp0;
        cst = g_c0; hout = g_h0[p ^ 1];
        ch0 = history + (b * LSEQ + t) * HW;           // x_t
        nx  = g_h0[p] + b * (HID0 * HW);               // h channels, contiguous
    } else {
        wp = g_wp1; bp = g_bp1;
        cst = g_c1; hout = g_h1[p ^ 1];
        ch0 = g_h0[p ^ 1] + b * (HID0 * HW);           // layer0 out, this step
        nx  = ch0 + HW;                                // channels 1..127 then h1
    }
    const float* h1base = (LAYER == 1) ? (g_h1[p] + b * (HID1 * HW)) : nullptr;

    __shared__ float2 smem[2][NTILE];    // duplicated lanes: .x == .y

    const int tid   = threadIdx.x;
    const int tx    = tid & 63;          // x coordinate
    const int ty    = tid >> 6;          // 0..3 row group
    const int k0    = blockIdx.y * KPB;
    const int y0    = blockIdx.x * C::TILEH;

    // Precompute tile-fill indices (constant across channels)
    int  pos_[FILLIT];
    bool val_[FILLIT];
    bool st_[FILLIT];
    #pragma unroll
    for (int u = 0; u < FILLIT; ++u) {
        int li = tid + u * 256;
        int rr = li / SCOLS;
        int cc = li - rr * SCOLS;
        int gy = y0 - 1 + rr;
        int gx = cc - 1;
        st_[u]  = (li < NTILE);
        val_[u] = st_[u] && gy >= 0 && gy < Hd && gx >= 0 && gx < Wd;
        pos_[u] = gy * Wd + gx;
    }

    auto fill = [&](const float* __restrict__ cp, float2* sn) {
        #pragma unroll
        for (int u = 0; u < FILLIT; ++u) {
            if (st_[u]) {
                float v = val_[u] ? __ldg(cp + pos_[u]) : 0.f;
                sn[tid + u * 256] = make_float2(v, v);
            }
        }
    };

    // accumulators: packed (i,f) and (o,g) for RPT rows x KPB channels
    u64t accIF[KPB][RPT], accOG[KPB][RPT];
    #pragma unroll
    for (int kk = 0; kk < KPB; ++kk) {
        float4 bk = bp[k0 + kk];
        u64t bif = pack2(bk.x, bk.y);
        u64t bog = pack2(bk.z, bk.w);
        #pragma unroll
        for (int r = 0; r < RPT; ++r) { accIF[kk][r] = bif; accOG[kk][r] = bog; }
    }

    const int base0 = (ty * RPT) * SCOLS + tx;
    const ulonglong2* wrun =
        reinterpret_cast<const ulonglong2*>(wp + (k0 * CIN) * 9);

    auto compute = [&](const float2* sb) {
        const u64t* st = reinterpret_cast<const u64t*>(sb);
        u64t ax[RPT + 2][3];
        #pragma unroll
        for (int i = 0; i < RPT + 2; ++i)
            #pragma unroll
            for (int j = 0; j < 3; ++j)
                ax[i][j] = st[base0 + i * SCOLS + j];
        #pragma unroll
        for (int kk = 0; kk < KPB; ++kk) {
            const ulonglong2* wc = wrun + kk * (CIN * 9);
            #pragma unroll
            for (int d = 0; d < 3; ++d) {
                ulonglong2 w0 = wc[d * 3 + 0];
                ulonglong2 w1 = wc[d * 3 + 1];
                ulonglong2 w2 = wc[d * 3 + 2];
                #pragma unroll
                for (int r = 0; r < RPT; ++r) {
                    const int i = d + r;
                    fma2ip(accIF[kk][r], w0.x, ax[i][0]);
                    fma2ip(accOG[kk][r], w0.y, ax[i][0]);
                    fma2ip(accIF[kk][r], w1.x, ax[i][1]);
                    fma2ip(accOG[kk][r], w1.y, ax[i][1]);
                    fma2ip(accIF[kk][r], w2.x, ax[i][2]);
                    fma2ip(accOG[kk][r], w2.y, ax[i][2]);
                }
            }
        }
        wrun += 9;
    };

    // advance nx to the next channel's base (handles layer1 srcA->srcB switch)
    int fillc = 1;   // channel index currently in nx
    auto advance = [&]() {
        if (LAYER == 1 && fillc + 1 == HID0) nx = h1base;
        else                                 nx = nx + HW;
        ++fillc;
    };

    // prologue: fill channel 0
    fill(ch0, smem[0]);
    __syncthreads();

    // main loop, 2x unrolled with compile-time buffer parity
    int c = 0;
    for (;;) {
        if (c + 1 < CIN) { fill(nx, smem[1]); advance(); }
        compute(smem[0]);
        __syncthreads();
        if (++c >= CIN) break;

        if (c + 1 < CIN) { fill(nx, smem[0]); advance(); }
        compute(smem[1]);
        __syncthreads();
        if (++c >= CIN) break;
    }

    // -------- LSTM gate epilogue: c' = sig(f)*c + sig(i)*tanh(g); h' = sig(o)*tanh(c')
    #pragma unroll
    for (int kk = 0; kk < KPB; ++kk) {
        const int kbase = (b * HIDN + (k0 + kk)) * HW;
        #pragma unroll
        for (int r = 0; r < RPT; ++r) {
            int y   = y0 + ty * RPT + r;
            int idx = kbase + y * Wd + tx;
            float zi, zf, zo, zg;
            unpack2(accIF[kk][r], zi, zf);
            unpack2(accOG[kk][r], zo, zg);
            float cprev = cst[idx];
            float cn = sigf(zf) * cprev + sigf(zi) * tanhf(zg);
            float hn = sigf(zo) * tanhf(cn);
            cst[idx]  = cn;
            hout[idx] = hn;
        }
    }
}

// ---------------- final output copy ------------------------------------------
// h_last of layer1 is (B,12,64,64) contiguous == (B,L,N,1) output layout.
__global__ void copy_out(float* __restrict__ out) {
    int i = blockIdx.x * blockDim.x + threadIdx.x;
    if (i < (Bsz * HID1 * HW) / 4)
        reinterpret_cast<float4*>(out)[i] =
            reinterpret_cast<const float4*>(g_h1[0])[i];
}

// ============================================================================
extern "C" void kernel_launch(void* const* d_in, const int* in_sizes, int n_in,
                              void* d_out, int out_size) {
    (void)in_sizes; (void)n_in; (void)out_size;
    const float* history = (const float*)d_in[0];   // (16,12,4096,1)
    const float* W0 = (const float*)d_in[2];        // (512,129,3,3)
    const float* b0 = (const float*)d_in[3];        // (512,)
    const float* W1 = (const float*)d_in[4];        // (48,140,3,3)
    const float* b1 = (const float*)d_in[5];        // (48,)
    float* out = (float*)d_out;

    // zero recurrent state (replay-deterministic)
    {
        int n4 = (Bsz * HID0 * HW) / 4;
        zero_state<<<(n4 + 255) / 256, 256>>>();
    }
    // weight/bias permutation
    prep_w<0><<<(HID0 * CIN0 * 9 + 255) / 256, 256>>>(W0, b0);
    prep_w<1><<<(HID1 * CIN1 * 9 + 255) / 256, 256>>>(W1, b1);

    // fused time loop: layer0 step t, then layer1 step t (consumes h0 of step t)
    for (int t = 0; t < LSEQ; ++t) {
        int p = t & 1;
        conv_step<0><<<dim3(Hd / Cfg<0>::TILEH, HID0 / Cfg<0>::KPB, Bsz), 256>>>(history, t, p);
        conv_step<1><<<dim3(Hd / Cfg<1>::TILEH, HID1 / Cfg<1>::KPB, Bsz), 256>>>(nullptr, t, p);
    }

    // after t=11, layer1 wrote h1[(11&1)^1] == h1[0]
    {
        int n4 = (Bsz * HID1 * HW) / 4;
        copy_out<<<(n4 + 255) / 256, 256>>>(out);
    }
}

// round 9
// speedup vs baseline: 1.0826x; 1.0826x over previous
#include <cuda_runtime.h>
#include <cuda_bf16.h>
#include <math.h>

// ============================================================================
// ConvLSTM (2 stacked layers, 12 timesteps) on GB300.
//   Layer0: Cin=129 (1 input + 128 hidden), hid=128
//   Layer1: Cin=140 (128 from layer0 + 12 hidden), hid=12
//   B=16, H=W=64.
// R9: fit 2 CTAs/SM *without* spills by construction: KPB=4, RPT=2, TILEH=8
//     -> ~93 regs demand (acc 32 + ax 24 + w 12 + misc ~25) under the 128 cap.
//     Keeps tied fma.rn.f32x2, duplicated-lane smem, incremental pointers.
// ============================================================================

#define Bsz  16
#define Hd   64
#define Wd   64
#define HW   4096
#define LSEQ 12

#define HID0 128
#define CIN0 129   // 1 + HID0
#define HID1 12
#define CIN1 140   // HID0 + HID1

#define SCOLS  66          // 64 + 2

typedef unsigned long long u64t;

// ---------------- per-layer tiling config ------------------------------------
template<int LAYER> struct Cfg;
template<> struct Cfg<0> {
    static constexpr int HIDN = 128, CIN = 129;
    static constexpr int KPB = 4, RPT = 2, TILEH = 8;
    static constexpr int SROWS = TILEH + 2;          // 10
    static constexpr int NTILE = SROWS * SCOLS;      // 660
    static constexpr int FILLIT = (NTILE + 255) / 256; // 3
    static constexpr int MINB = 2;                   // 2 CTAs/SM, no spills
};
template<> struct Cfg<1> {
    static constexpr int HIDN = 12, CIN = 140;
    static constexpr int KPB = 2, RPT = 2, TILEH = 8;
    static constexpr int SROWS = TILEH + 2;          // 10
    static constexpr int NTILE = SROWS * SCOLS;      // 660
    static constexpr int FILLIT = (NTILE + 255) / 256; // 3
    static constexpr int MINB = 2;
};

// ---------------- persistent device state (no runtime allocation) ----------
__device__ __align__(16) float g_h0[2][Bsz*HID0*HW];   // ping-pong hidden, layer0
__device__ __align__(16) float g_c0[Bsz*HID0*HW];
__device__ __align__(16) float g_h1[2][Bsz*HID1*HW];
__device__ __align__(16) float g_c1[Bsz*HID1*HW];
__device__ float4 g_wp0[HID0*CIN0*9];   // [k][c][tap] -> (wi,wf,wo,wg)
__device__ float4 g_bp0[HID0];
__device__ float4 g_wp1[HID1*CIN1*9];
__device__ float4 g_bp1[HID1];

// ---------------- packed f32x2 helpers --------------------------------------
__device__ __forceinline__ u64t pack2(float a, float b) {
    u64t r;
    asm("mov.b64 %0, {%1, %2};" : "=l"(r) : "f"(a), "f"(b));
    return r;
}
// In-place accumulate: tied "+l" constraint -> no destination copy.
__device__ __forceinline__ void fma2ip(u64t& acc, u64t a, u64t b) {
    asm("fma.rn.f32x2 %0, %1, %2, %0;" : "+l"(acc) : "l"(a), "l"(b));
}
__device__ __forceinline__ void unpack2(u64t v, float& lo, float& hi) {
    asm("mov.b64 {%0, %1}, %2;" : "=f"(lo), "=f"(hi) : "l"(v));
}

__device__ __forceinline__ float sigf(float x) { return 1.0f / (1.0f + expf(-x)); }

// ---------------- weight/bias permutation -----------------------------------
// W layout in: [gate*HID + k][c][kh][kw]  ->  out: [k][c][tap] float4(gates)
template<int LAYER>
__global__ void prep_w(const float* __restrict__ W, const float* __restrict__ bias) {
    constexpr int HIDN = Cfg<LAYER>::HIDN;
    constexpr int CIN  = Cfg<LAYER>::CIN;
    float4* wp = (LAYER == 0) ? g_wp0 : g_wp1;
    float4* bp = (LAYER == 0) ? g_bp0 : g_bp1;

    int i = blockIdx.x * blockDim.x + threadIdx.x;
    if (i < HIDN * CIN * 9) {
        int tap = i % 9;
        int c   = (i / 9) % CIN;
        int k   = i / (9 * CIN);
        float4 v;
        v.x = W[((0 * HIDN + k) * CIN + c) * 9 + tap];   // i gate
        v.y = W[((1 * HIDN + k) * CIN + c) * 9 + tap];   // f gate
        v.z = W[((2 * HIDN + k) * CIN + c) * 9 + tap];   // o gate
        v.w = W[((3 * HIDN + k) * CIN + c) * 9 + tap];   // g gate
        wp[i] = v;
    }
    if (i < HIDN) {
        bp[i] = make_float4(bias[0 * HIDN + i], bias[1 * HIDN + i],
                            bias[2 * HIDN + i], bias[3 * HIDN + i]);
    }
}

// ---------------- state zeroing (every launch: deterministic replays) -------
__global__ void zero_state() {
    int i = blockIdx.x * blockDim.x + threadIdx.x;
    float4 z = make_float4(0.f, 0.f, 0.f, 0.f);
    if (i < (Bsz * HID0 * HW) / 4) {
        reinterpret_cast<float4*>(g_h0[0])[i] = z;
        reinterpret_cast<float4*>(g_c0)[i]    = z;
    }
    if (i < (Bsz * HID1 * HW) / 4) {
        reinterpret_cast<float4*>(g_h1[0])[i] = z;
        reinterpret_cast<float4*>(g_c1)[i]    = z;
    }
}

// ---------------- fused conv + LSTM gate step --------------------------------
// grid: (Hd/TILEH y-tiles, HIDN/KPB, B), block: 256 threads.
// Each thread: one x-column, RPT consecutive rows, KPB output channels.
// Activation tiles: duplicated-lane float2 in smem -> one LDS.64 = packed op.
template<int LAYER>
__global__ __launch_bounds__(256, Cfg<LAYER>::MINB)
void conv_step(const float* __restrict__ history, int t, int p) {
    using C = Cfg<LAYER>;
    constexpr int HIDN = C::HIDN;
    constexpr int CIN  = C::CIN;
    constexpr int KPB  = C::KPB;
    constexpr int RPT  = C::RPT;
    constexpr int FILLIT = C::FILLIT;
    constexpr int NTILE  = C::NTILE;

    const float4* __restrict__ wp;
    const float4* __restrict__ bp;
    float* cst;
    float* hout;
    const float* ch0;     // pointer to channel 0 for this batch
    const float* nx;      // pointer to next fill channel (starts at channel 1)
    const int b = blockIdx.z;

    if (LAYER == 0) {
        wp = g_wp0; bp = g_bp0;
        cst = g_c0; hout = g_h0[p ^ 1];
        ch0 = history + (b * LSEQ + t) * HW;           // x_t
        nx  = g_h0[p] + b * (HID0 * HW);               // h channels, contiguous
    } else {
        wp = g_wp1; bp = g_bp1;
        cst = g_c1; hout = g_h1[p ^ 1];
        ch0 = g_h0[p ^ 1] + b * (HID0 * HW);           // layer0 out, this step
        nx  = ch0 + HW;                                // channels 1..127 then h1
    }
    const float* h1base = (LAYER == 1) ? (g_h1[p] + b * (HID1 * HW)) : nullptr;

    __shared__ float2 smem[2][NTILE];    // duplicated lanes: .x == .y

    const int tid   = threadIdx.x;
    const int tx    = tid & 63;          // x coordinate
    const int ty    = tid >> 6;          // 0..3 row group
    const int k0    = blockIdx.y * KPB;
    const int y0    = blockIdx.x * C::TILEH;

    // Precompute tile-fill indices (constant across channels)
    int  pos_[FILLIT];
    bool val_[FILLIT];
    bool st_[FILLIT];
    #pragma unroll
    for (int u = 0; u < FILLIT; ++u) {
        int li = tid + u * 256;
        int rr = li / SCOLS;
        int cc = li - rr * SCOLS;
        int gy = y0 - 1 + rr;
        int gx = cc - 1;
        st_[u]  = (li < NTILE);
        val_[u] = st_[u] && gy >= 0 && gy < Hd && gx >= 0 && gx < Wd;
        pos_[u] = gy * Wd + gx;
    }

    auto fill = [&](const float* __restrict__ cp, float2* sn) {
        #pragma unroll
        for (int u = 0; u < FILLIT; ++u) {
            if (st_[u]) {
                float v = val_[u] ? __ldg(cp + pos_[u]) : 0.f;
                sn[tid + u * 256] = make_float2(v, v);
            }
        }
    };

    // accumulators: packed (i,f) and (o,g) for RPT rows x KPB channels
    u64t accIF[KPB][RPT], accOG[KPB][RPT];
    #pragma unroll
    for (int kk = 0; kk < KPB; ++kk) {
        float4 bk = bp[k0 + kk];
        u64t bif = pack2(bk.x, bk.y);
        u64t bog = pack2(bk.z, bk.w);
        #pragma unroll
        for (int r = 0; r < RPT; ++r) { accIF[kk][r] = bif; accOG[kk][r] = bog; }
    }

    const int base0 = (ty * RPT) * SCOLS + tx;
    const ulonglong2* wrun =
        reinterpret_cast<const ulonglong2*>(wp + (k0 * CIN) * 9);

    auto compute = [&](const float2* sb) {
        const u64t* st = reinterpret_cast<const u64t*>(sb);
        u64t ax[RPT + 2][3];
        #pragma unroll
        for (int i = 0; i < RPT + 2; ++i)
            #pragma unroll
            for (int j = 0; j < 3; ++j)
                ax[i][j] = st[base0 + i * SCOLS + j];
        #pragma unroll
        for (int kk = 0; kk < KPB; ++kk) {
            const ulonglong2* wc = wrun + kk * (CIN * 9);
            #pragma unroll
            for (int d = 0; d < 3; ++d) {
                ulonglong2 w0 = wc[d * 3 + 0];
                ulonglong2 w1 = wc[d * 3 + 1];
                ulonglong2 w2 = wc[d * 3 + 2];
                #pragma unroll
                for (int r = 0; r < RPT; ++r) {
                    const int i = d + r;
                    fma2ip(accIF[kk][r], w0.x, ax[i][0]);
                    fma2ip(accOG[kk][r], w0.y, ax[i][0]);
                    fma2ip(accIF[kk][r], w1.x, ax[i][1]);
                    fma2ip(accOG[kk][r], w1.y, ax[i][1]);
                    fma2ip(accIF[kk][r], w2.x, ax[i][2]);
                    fma2ip(accOG[kk][r], w2.y, ax[i][2]);
                }
            }
        }
        wrun += 9;
    };

    // advance nx to the next channel's base (handles layer1 srcA->srcB switch)
    int fillc = 1;   // channel index currently in nx
    auto advance = [&]() {
        if (LAYER == 1 && fillc + 1 == HID0) nx = h1base;
        else                                 nx = nx + HW;
        ++fillc;
    };

    // prologue: fill channel 0
    fill(ch0, smem[0]);
    __syncthreads();

    // main loop, 2x unrolled with compile-time buffer parity
    int c = 0;
    for (;;) {
        if (c + 1 < CIN) { fill(nx, smem[1]); advance(); }
        compute(smem[0]);
        __syncthreads();
        if (++c >= CIN) break;

        if (c + 1 < CIN) { fill(nx, smem[0]); advance(); }
        compute(smem[1]);
        __syncthreads();
        if (++c >= CIN) break;
    }

    // -------- LSTM gate epilogue: c' = sig(f)*c + sig(i)*tanh(g); h' = sig(o)*tanh(c')
    #pragma unroll
    for (int kk = 0; kk < KPB; ++kk) {
        const int kbase = (b * HIDN + (k0 + kk)) * HW;
        #pragma unroll
        for (int r = 0; r < RPT; ++r) {
            int y   = y0 + ty * RPT + r;
            int idx = kbase + y * Wd + tx;
            float zi, zf, zo, zg;
            unpack2(accIF[kk][r], zi, zf);
            unpack2(accOG[kk][r], zo, zg);
            float cprev = cst[idx];
            float cn = sigf(zf) * cprev + sigf(zi) * tanhf(zg);
            float hn = sigf(zo) * tanhf(cn);
            cst[idx]  = cn;
            hout[idx] = hn;
        }
    }
}

// ---------------- final output copy ------------------------------------------
// h_last of layer1 is (B,12,64,64) contiguous == (B,L,N,1) output layout.
__global__ void copy_out(float* __restrict__ out) {
    int i = blockIdx.x * blockDim.x + threadIdx.x;
    if (i < (Bsz * HID1 * HW) / 4)
        reinterpret_cast<float4*>(out)[i] =
            reinterpret_cast<const float4*>(g_h1[0])[i];
}

// ============================================================================
extern "C" void kernel_launch(void* const* d_in, const int* in_sizes, int n_in,
                              void* d_out, int out_size) {
    (void)in_sizes; (void)n_in; (void)out_size;
    const float* history = (const float*)d_in[0];   // (16,12,4096,1)
    const float* W0 = (const float*)d_in[2];        // (512,129,3,3)
    const float* b0 = (const float*)d_in[3];        // (512,)
    const float* W1 = (const float*)d_in[4];        // (48,140,3,3)
    const float* b1 = (const float*)d_in[5];        // (48,)
    float* out = (float*)d_out;

    // zero recurrent state (replay-deterministic)
    {
        int n4 = (Bsz * HID0 * HW) / 4;
        zero_state<<<(n4 + 255) / 256, 256>>>();
    }
    // weight/bias permutation
    prep_w<0><<<(HID0 * CIN0 * 9 + 255) / 256, 256>>>(W0, b0);
    prep_w<1><<<(HID1 * CIN1 * 9 + 255) / 256, 256>>>(W1, b1);

    // fused time loop: layer0 step t, then layer1 step t (consumes h0 of step t)
    for (int t = 0; t < LSEQ; ++t) {
        int p = t & 1;
        conv_step<0><<<dim3(Hd / Cfg<0>::TILEH, HID0 / Cfg<0>::KPB, Bsz), 256>>>(history, t, p);
        conv_step<1><<<dim3(Hd / Cfg<1>::TILEH, HID1 / Cfg<1>::KPB, Bsz), 256>>>(nullptr, t, p);
    }

    // after t=11, layer1 wrote h1[(11&1)^1] == h1[0]
    {
        int n4 = (Bsz * HID1 * HW) / 4;
        copy_out<<<(n4 + 255) / 256, 256>>>(out);
    }
}

// round 10
// speedup vs baseline: 1.5418x; 1.4242x over previous
#include <cuda_runtime.h>
#include <cuda_bf16.h>
#include <math.h>

// ============================================================================
// ConvLSTM (2 stacked layers, 12 timesteps) on GB300.
//   Layer0: Cin=129 (1 input + 128 hidden), hid=128
//   Layer1: Cin=140 (128 from layer0 + 12 hidden), hid=12
//   B=16, H=W=64.
// R10: padded-halo (66x66) activation buffers -> contiguous unconditional
//      tile fill (kills predicate/index registers and SELs); unified input
//      layout (slot0 = x_t) -> branch-free channel march for layer0; simple
//      rolled loop (no liveness-doubling unroll). KPB=4/RPT=4 @ 2 CTAs/SM.
// ============================================================================

#define Bsz  16
#define Hd   64
#define Wd   64
#define HW   4096
#define LSEQ 12

#define HID0 128
#define CIN0 129
#define HID1 12
#define CIN1 140

#define PW   66            // padded row stride
#define CHP  (66*66)       // padded channel size = 4356
#define NT   1188          // tile floats = 18*66

typedef unsigned long long u64t;

// ---------------- per-layer tiling config ------------------------------------
template<int LAYER> struct Cfg;
template<> struct Cfg<0> {
    static constexpr int HIDN = 128, CIN = 129;
    static constexpr int KPB = 4, RPT = 4, TILEH = 16;
};
template<> struct Cfg<1> {
    static constexpr int HIDN = 12, CIN = 140;
    static constexpr int KPB = 2, RPT = 4, TILEH = 16;
};

// ---------------- persistent device state (no runtime allocation) ----------
// g_a0[p]: per batch, 129 padded channel slots: [0]=x_t, [1..128]=h0
__device__ __align__(16) float g_a0[2][Bsz*CIN0*CHP];
__device__ __align__(16) float g_h1p[2][Bsz*HID1*CHP];   // padded h1
__device__ __align__(16) float g_c0[Bsz*HID0*HW];        // unpadded c
__device__ __align__(16) float g_c1[Bsz*HID1*HW];
__device__ float4 g_wp0[HID0*CIN0*9];   // [k][c][tap] -> (wi,wf,wo,wg)
__device__ float4 g_bp0[HID0];
__device__ float4 g_wp1[HID1*CIN1*9];
__device__ float4 g_bp1[HID1];

// ---------------- packed f32x2 helpers --------------------------------------
__device__ __forceinline__ u64t pack2(float a, float b) {
    u64t r;
    asm("mov.b64 %0, {%1, %2};" : "=l"(r) : "f"(a), "f"(b));
    return r;
}
__device__ __forceinline__ void fma2ip(u64t& acc, u64t a, u64t b) {
    asm("fma.rn.f32x2 %0, %1, %2, %0;" : "+l"(acc) : "l"(a), "l"(b));
}
__device__ __forceinline__ void unpack2(u64t v, float& lo, float& hi) {
    asm("mov.b64 {%0, %1}, %2;" : "=f"(lo), "=f"(hi) : "l"(v));
}
__device__ __forceinline__ float sigf(float x) { return 1.0f / (1.0f + expf(-x)); }

// ---------------- weight/bias permutation -----------------------------------
template<int LAYER>
__global__ void prep_w(const float* __restrict__ W, const float* __restrict__ bias) {
    constexpr int HIDN = Cfg<LAYER>::HIDN;
    constexpr int CIN  = Cfg<LAYER>::CIN;
    float4* wp = (LAYER == 0) ? g_wp0 : g_wp1;
    float4* bp = (LAYER == 0) ? g_bp0 : g_bp1;

    int i = blockIdx.x * blockDim.x + threadIdx.x;
    if (i < HIDN * CIN * 9) {
        int tap = i % 9;
        int c   = (i / 9) % CIN;
        int k   = i / (9 * CIN);
        float4 v;
        v.x = W[((0 * HIDN + k) * CIN + c) * 9 + tap];
        v.y = W[((1 * HIDN + k) * CIN + c) * 9 + tap];
        v.z = W[((2 * HIDN + k) * CIN + c) * 9 + tap];
        v.w = W[((3 * HIDN + k) * CIN + c) * 9 + tap];
        wp[i] = v;
    }
    if (i < HIDN) {
        bp[i] = make_float4(bias[0 * HIDN + i], bias[1 * HIDN + i],
                            bias[2 * HIDN + i], bias[3 * HIDN + i]);
    }
}

// ---------------- state zeroing (every launch: deterministic replays) -------
__global__ void zero_state() {
    long i = (long)blockIdx.x * blockDim.x + threadIdx.x;
    float4 z = make_float4(0.f, 0.f, 0.f, 0.f);
    if (i < (long)2 * Bsz * CIN0 * CHP / 4) reinterpret_cast<float4*>(g_a0)[i]  = z;
    if (i < (long)2 * Bsz * HID1 * CHP / 4) reinterpret_cast<float4*>(g_h1p)[i] = z;
    if (i < (long)Bsz * HID0 * HW / 4)      reinterpret_cast<float4*>(g_c0)[i]  = z;
    if (i < (long)Bsz * HID1 * HW / 4)      reinterpret_cast<float4*>(g_c1)[i]  = z;
}

// ---------------- x padding: write x_t into slot 0 of input buffer p ---------
__global__ void pad_x(const float* __restrict__ hist, int t, int p) {
    int i = blockIdx.x * blockDim.x + threadIdx.x;   // Bsz*HW
    if (i < Bsz * HW) {
        int b = i >> 12;
        int r = i & 4095;
        int y = r >> 6, x = r & 63;
        g_a0[p][b * (CIN0 * CHP) + (y + 1) * PW + (x + 1)] =
            hist[(b * LSEQ + t) * HW + r];
    }
}

// ---------------- fused conv + LSTM gate step --------------------------------
// grid: (4 y-tiles, HIDN/KPB, B), block: 256 threads.
// Tile = contiguous 1188-float span of the padded channel starting at row y0.
template<int LAYER>
__global__ __launch_bounds__(256, 2)
void conv_step(int t, int p) {
    using C = Cfg<LAYER>;
    constexpr int HIDN = C::HIDN;
    constexpr int CIN  = C::CIN;
    constexpr int KPB  = C::KPB;
    constexpr int RPT  = C::RPT;

    const int b = blockIdx.z;
    const float* inA;
    const float* inB = nullptr;
    float* houtp;     // padded h output, k-slot base
    float* cst;       // unpadded c, batch base
    const float4* __restrict__ wp;
    const float4* __restrict__ bp;

    if (LAYER == 0) {
        inA   = g_a0[p] + b * (CIN0 * CHP);                 // slots 0..128
        houtp = g_a0[p ^ 1] + b * (CIN0 * CHP) + CHP;       // k -> slot k+1
        cst   = g_c0 + b * (HID0 * HW);
        wp = g_wp0; bp = g_bp0;
    } else {
        inA   = g_a0[p ^ 1] + b * (CIN0 * CHP) + CHP;       // h0(t), 128 ch
        inB   = g_h1p[p] + b * (HID1 * CHP);                // h1(t-1), 12 ch
        houtp = g_h1p[p ^ 1] + b * (HID1 * CHP);
        cst   = g_c1 + b * (HID1 * HW);
        wp = g_wp1; bp = g_bp1;
    }

    __shared__ float2 smem[2][NT];       // duplicated lanes: .x == .y

    const int tid = threadIdx.x;
    const int tx  = tid & 63;
    const int ty  = tid >> 6;
    const int k0  = blockIdx.y * KPB;
    const int y0  = blockIdx.x * C::TILEH;
    const int fo  = y0 * PW + tid;       // fill base offset into padded channel

    // accumulators: packed (i,f) and (o,g), init with bias
    u64t accIF[KPB][RPT], accOG[KPB][RPT];
    #pragma unroll
    for (int kk = 0; kk < KPB; ++kk) {
        float4 bk = bp[k0 + kk];
        u64t bif = pack2(bk.x, bk.y);
        u64t bog = pack2(bk.z, bk.w);
        #pragma unroll
        for (int r = 0; r < RPT; ++r) { accIF[kk][r] = bif; accOG[kk][r] = bog; }
    }

    const int base0 = (ty * RPT) * PW + tx;
    const ulonglong2* wrun =
        reinterpret_cast<const ulonglong2*>(wp + (k0 * CIN) * 9);

    auto compute = [&](const float2* sb) {
        const u64t* st = reinterpret_cast<const u64t*>(sb);
        u64t ax[RPT + 2][3];
        #pragma unroll
        for (int i = 0; i < RPT + 2; ++i)
            #pragma unroll
            for (int j = 0; j < 3; ++j)
                ax[i][j] = st[base0 + i * PW + j];
        #pragma unroll
        for (int kk = 0; kk < KPB; ++kk) {
            const ulonglong2* wc = wrun + kk * (CIN * 9);
            #pragma unroll
            for (int d = 0; d < 3; ++d) {
                ulonglong2 w0 = wc[d * 3 + 0];
                ulonglong2 w1 = wc[d * 3 + 1];
                ulonglong2 w2 = wc[d * 3 + 2];
                #pragma unroll
                for (int r = 0; r < RPT; ++r) {
                    const int i = d + r;
                    fma2ip(accIF[kk][r], w0.x, ax[i][0]);
                    fma2ip(accOG[kk][r], w0.y, ax[i][0]);
                    fma2ip(accIF[kk][r], w1.x, ax[i][1]);
                    fma2ip(accOG[kk][r], w1.y, ax[i][1]);
                    fma2ip(accIF[kk][r], w2.x, ax[i][2]);
                    fma2ip(accOG[kk][r], w2.y, ax[i][2]);
                }
            }
        }
        wrun += 9;
    };

    // prologue: fill channel 0 (contiguous, only last iter predicated)
    {
        #pragma unroll
        for (int u = 0; u < 5; ++u) {
            int li = tid + u * 256;
            if (u < 4 || li < NT) {
                float v = __ldg(inA + fo + u * 256);
                smem[0][li] = make_float2(v, v);
            }
        }
    }
    __syncthreads();

    const float* nx = inA + CHP;         // next fill channel (ch 1)
    int par = 0;
    for (int c = 0; c < CIN - 1; ++c) {
        // prefetch channel c+1 into registers
        float pf[5];
        #pragma unroll
        for (int u = 0; u < 5; ++u) {
            int li = tid + u * 256;
            if (u < 4 || li < NT) pf[u] = __ldg(nx + fo + u * 256);
        }

        compute(smem[par]);

        float2* sn = smem[par ^ 1];
        #pragma unroll
        for (int u = 0; u < 5; ++u) {
            int li = tid + u * 256;
            if (u < 4 || li < NT) sn[li] = make_float2(pf[u], pf[u]);
        }
        __syncthreads();
        par ^= 1;
        nx += CHP;
        if (LAYER == 1 && c + 2 == 128) nx = inB;   // switch to h1 region
    }
    compute(smem[par]);                  // last channel

    // -------- LSTM gate epilogue ---------------------------------------------
    #pragma unroll
    for (int kk = 0; kk < KPB; ++kk) {
        const int k = k0 + kk;
        #pragma unroll
        for (int r = 0; r < RPT; ++r) {
            int y  = y0 + ty * RPT + r;
            int ci = k * HW + y * Wd + tx;
            float zi, zf, zo, zg;
            unpack2(accIF[kk][r], zi, zf);
            unpack2(accOG[kk][r], zo, zg);
            float cprev = cst[ci];
            float cn = sigf(zf) * cprev + sigf(zi) * tanhf(zg);
            float hn = sigf(zo) * tanhf(cn);
            cst[ci] = cn;
            houtp[k * CHP + (y + 1) * PW + (tx + 1)] = hn;
        }
    }
}

// ---------------- final output copy ------------------------------------------
// h_last of layer1 (padded) -> (B, 12, 4096, 1) contiguous output.
__global__ void copy_out(float* __restrict__ out) {
    int i = blockIdx.x * blockDim.x + threadIdx.x;
    if (i < Bsz * HID1 * HW) {
        int b = i / (HID1 * HW);
        int r = i % (HID1 * HW);
        int k = r >> 12;
        int s = r & 4095;
        int y = s >> 6, x = s & 63;
        out[i] = g_h1p[0][b * (HID1 * CHP) + k * CHP + (y + 1) * PW + (x + 1)];
    }
}

// ============================================================================
extern "C" void kernel_launch(void* const* d_in, const int* in_sizes, int n_in,
                              void* d_out, int out_size) {
    (void)in_sizes; (void)n_in; (void)out_size;
    const float* history = (const float*)d_in[0];   // (16,12,4096,1)
    const float* W0 = (const float*)d_in[2];        // (512,129,3,3)
    const float* b0 = (const float*)d_in[3];        // (512,)
    const float* W1 = (const float*)d_in[4];        // (48,140,3,3)
    const float* b1 = (const float*)d_in[5];        // (48,)
    float* out = (float*)d_out;

    // zero all state (halos stay zero; replay-deterministic)
    {
        long n4 = (long)2 * Bsz * CIN0 * CHP / 4;
        zero_state<<<(unsigned)((n4 + 255) / 256), 256>>>();
    }
    prep_w<0><<<(HID0 * CIN0 * 9 + 255) / 256, 256>>>(W0, b0);
    prep_w<1><<<(HID1 * CIN1 * 9 + 255) / 256, 256>>>(W1, b1);

    for (int t = 0; t < LSEQ; ++t) {
        int p = t & 1;
        pad_x<<<(Bsz * HW + 255) / 256, 256>>>(history, t, p);
        conv_step<0><<<dim3(Hd / Cfg<0>::TILEH, HID0 / Cfg<0>::KPB, Bsz), 256>>>(t, p);
        conv_step<1><<<dim3(Hd / Cfg<1>::TILEH, HID1 / Cfg<1>::KPB, Bsz), 256>>>(t, p);
    }

    // after t=11 (p=1), layer1 wrote h1 into g_h1p[0]
    copy_out<<<(Bsz * HID1 * HW + 255) / 256, 256>>>(out);
}

// round 15
// speedup vs baseline: 1.9001x; 1.2324x over previous
#include <cuda_runtime.h>
#include <cuda_bf16.h>
#include <math.h>

// ============================================================================
// ConvLSTM (2 stacked layers, 12 timesteps) on GB300.
//   Layer0: Cin=129 (1 input + 128 hidden), hid=128
//   Layer1: Cin=140 (128 from layer0 + 12 hidden), hid=12
//   B=16, H=W=64.
// R11: break the 128-reg cap by occupancy geometry: 128-thread blocks with
//      __launch_bounds__(128,3) -> 170-reg budget, demand ~160 -> NO spills.
//      Shape KPB=2, RPT=8 (TILEH=16): 288 fma2 per channel per thread vs
//      ~60 non-fma -> ~82% fma issue share. 12 warps/SM (3 CTAs) keeps the
//      fma pipe fed. Padded-halo buffers + tied fma.rn.f32x2 carried over.
// ============================================================================

#define Bsz  16
#define Hd   64
#define Wd   64
#define HW   4096
#define LSEQ 12

#define HID0 128
#define CIN0 129
#define HID1 12
#define CIN1 140

#define PW   66            // padded row stride
#define CHP  (66*66)       // padded channel size = 4356
#define NT   1188          // tile floats = 18*66
#define NT2  594           // tile float2 count
#define THR  128           // threads per block

typedef unsigned long long u64t;

// ---------------- per-layer tiling config ------------------------------------
template<int LAYER> struct Cfg;
template<> struct Cfg<0> {
    static constexpr int HIDN = 128, CIN = 129;
    static constexpr int KPB = 2, RPT = 8, TILEH = 16;
};
template<> struct Cfg<1> {
    static constexpr int HIDN = 12, CIN = 140;
    static constexpr int KPB = 2, RPT = 8, TILEH = 16;
};

// ---------------- persistent device state (no runtime allocation) ----------
// g_a0[p]: per batch, 129 padded channel slots: [0]=x_t, [1..128]=h0
__device__ __align__(16) float g_a0[2][Bsz*CIN0*CHP];
__device__ __align__(16) float g_h1p[2][Bsz*HID1*CHP];   // padded h1
__device__ __align__(16) float g_c0[Bsz*HID0*HW];        // unpadded c
__device__ __align__(16) float g_c1[Bsz*HID1*HW];
__device__ float4 g_wp0[HID0*CIN0*9];   // [k][c][tap] -> (wi,wf,wo,wg)
__device__ float4 g_bp0[HID0];
__device__ float4 g_wp1[HID1*CIN1*9];
__device__ float4 g_bp1[HID1];

// ---------------- packed f32x2 helpers --------------------------------------
__device__ __forceinline__ u64t pack2(float a, float b) {
    u64t r;
    asm("mov.b64 %0, {%1, %2};" : "=l"(r) : "f"(a), "f"(b));
    return r;
}
__device__ __forceinline__ void fma2ip(u64t& acc, u64t a, u64t b) {
    asm("fma.rn.f32x2 %0, %1, %2, %0;" : "+l"(acc) : "l"(a), "l"(b));
}
__device__ __forceinline__ void unpack2(u64t v, float& lo, float& hi) {
    asm("mov.b64 {%0, %1}, %2;" : "=f"(lo), "=f"(hi) : "l"(v));
}
__device__ __forceinline__ float sigf(float x) { return 1.0f / (1.0f + expf(-x)); }

// ---------------- weight/bias permutation -----------------------------------
template<int LAYER>
__global__ void prep_w(const float* __restrict__ W, const float* __restrict__ bias) {
    constexpr int HIDN = Cfg<LAYER>::HIDN;
    constexpr int CIN  = Cfg<LAYER>::CIN;
    float4* wp = (LAYER == 0) ? g_wp0 : g_wp1;
    float4* bp = (LAYER == 0) ? g_bp0 : g_bp1;

    int i = blockIdx.x * blockDim.x + threadIdx.x;
    if (i < HIDN * CIN * 9) {
        int tap = i % 9;
        int c   = (i / 9) % CIN;
        int k   = i / (9 * CIN);
        float4 v;
        v.x = W[((0 * HIDN + k) * CIN + c) * 9 + tap];
        v.y = W[((1 * HIDN + k) * CIN + c) * 9 + tap];
        v.z = W[((2 * HIDN + k) * CIN + c) * 9 + tap];
        v.w = W[((3 * HIDN + k) * CIN + c) * 9 + tap];
        wp[i] = v;
    }
    if (i < HIDN) {
        bp[i] = make_float4(bias[0 * HIDN + i], bias[1 * HIDN + i],
                            bias[2 * HIDN + i], bias[3 * HIDN + i]);
    }
}

// ---------------- state zeroing (every launch: deterministic replays) -------
__global__ void zero_state() {
    long i = (long)blockIdx.x * blockDim.x + threadIdx.x;
    float4 z = make_float4(0.f, 0.f, 0.f, 0.f);
    if (i < (long)2 * Bsz * CIN0 * CHP / 4) reinterpret_cast<float4*>(g_a0)[i]  = z;
    if (i < (long)2 * Bsz * HID1 * CHP / 4) reinterpret_cast<float4*>(g_h1p)[i] = z;
    if (i < (long)Bsz * HID0 * HW / 4)      reinterpret_cast<float4*>(g_c0)[i]  = z;
    if (i < (long)Bsz * HID1 * HW / 4)      reinterpret_cast<float4*>(g_c1)[i]  = z;
}

// ---------------- x padding: write x_t into slot 0 of input buffer p ---------
__global__ void pad_x(const float* __restrict__ hist, int t, int p) {
    int i = blockIdx.x * blockDim.x + threadIdx.x;   // Bsz*HW
    if (i < Bsz * HW) {
        int b = i >> 12;
        int r = i & 4095;
        int y = r >> 6, x = r & 63;
        g_a0[p][b * (CIN0 * CHP) + (y + 1) * PW + (x + 1)] =
            hist[(b * LSEQ + t) * HW + r];
    }
}

// ---------------- fused conv + LSTM gate step --------------------------------
// grid: (4 y-tiles, HIDN/KPB, B), block: 128 threads (64 x-cols x 2 row-groups).
// Each thread: one x-column, 8 consecutive rows, 2 output channels, 4 gates.
template<int LAYER>
__global__ __launch_bounds__(THR, 3)
void conv_step(int t, int p) {
    using C = Cfg<LAYER>;
    constexpr int CIN  = C::CIN;
    constexpr int KPB  = C::KPB;
    constexpr int RPT  = C::RPT;

    const int b = blockIdx.z;
    const float* inA;
    const float* inB = nullptr;
    float* houtp;     // padded h output, batch base
    float* cst;       // unpadded c, batch base
    const float4* __restrict__ wp;
    const float4* __restrict__ bp;

    if (LAYER == 0) {
        inA   = g_a0[p] + b * (CIN0 * CHP);                 // slots 0..128
        houtp = g_a0[p ^ 1] + b * (CIN0 * CHP) + CHP;       // k -> slot k+1
        cst   = g_c0 + b * (HID0 * HW);
        wp = g_wp0; bp = g_bp0;
    } else {
        inA   = g_a0[p ^ 1] + b * (CIN0 * CHP) + CHP;       // h0(t), 128 ch
        inB   = g_h1p[p] + b * (HID1 * CHP);                // h1(t-1), 12 ch
        houtp = g_h1p[p ^ 1] + b * (HID1 * CHP);
        cst   = g_c1 + b * (HID1 * HW);
        wp = g_wp1; bp = g_bp1;
    }

    __shared__ float2 smem[2][NT];       // duplicated lanes: .x == .y

    const int tid = threadIdx.x;
    const int tx  = tid & 63;
    const int ty  = tid >> 6;            // 0..1
    const int k0  = blockIdx.y * KPB;
    const int y0  = blockIdx.x * C::TILEH;
    const int fo2 = (y0 * PW) / 2 + tid; // fill base in float2 units (aligned)

    // accumulators: packed (i,f) and (o,g), init with bias
    u64t accIF[KPB][RPT], accOG[KPB][RPT];
    #pragma unroll
    for (int kk = 0; kk < KPB; ++kk) {
        float4 bk = bp[k0 + kk];
        u64t bif = pack2(bk.x, bk.y);
        u64t bog = pack2(bk.z, bk.w);
        #pragma unroll
        for (int r = 0; r < RPT; ++r) { accIF[kk][r] = bif; accOG[kk][r] = bog; }
    }

    const int base0 = (ty * RPT) * PW + tx;
    const ulonglong2* wrun =
        reinterpret_cast<const ulonglong2*>(wp + (k0 * CIN) * 9);

    auto compute = [&](const float2* sb) {
        const u64t* st = reinterpret_cast<const u64t*>(sb);
        u64t ax[RPT + 2][3];
        #pragma unroll
        for (int i = 0; i < RPT + 2; ++i)
            #pragma unroll
            for (int j = 0; j < 3; ++j)
                ax[i][j] = st[base0 + i * PW + j];
        #pragma unroll
        for (int kk = 0; kk < KPB; ++kk) {
            const ulonglong2* wc = wrun + kk * (CIN * 9);
            #pragma unroll
            for (int d = 0; d < 3; ++d) {
                ulonglong2 w0 = wc[d * 3 + 0];
                ulonglong2 w1 = wc[d * 3 + 1];
                ulonglong2 w2 = wc[d * 3 + 2];
                #pragma unroll
                for (int r = 0; r < RPT; ++r) {
                    const int i = d + r;
                    fma2ip(accIF[kk][r], w0.x, ax[i][0]);
                    fma2ip(accOG[kk][r], w0.y, ax[i][0]);
                    fma2ip(accIF[kk][r], w1.x, ax[i][1]);
                    fma2ip(accOG[kk][r], w1.y, ax[i][1]);
                    fma2ip(accIF[kk][r], w2.x, ax[i][2]);
                    fma2ip(accOG[kk][r], w2.y, ax[i][2]);
                }
            }
        }
        wrun += 9;
    };

    // prologue: fill channel 0 (contiguous float2 spans of padded channel)
    {
        const float2* cp = reinterpret_cast<const float2*>(inA) + fo2;
        float4* s4 = reinterpret_cast<float4*>(smem[0]);
        #pragma unroll
        for (int u = 0; u < 5; ++u) {
            int li = tid + u * THR;
            if (u < 4 || li < NT2) {
                float2 v = __ldg(cp + u * THR);
                s4[li] = make_float4(v.x, v.x, v.y, v.y);
            }
        }
    }
    __syncthreads();

    const float* nx = inA + CHP;         // next fill channel (ch 1)
    int par = 0;
    for (int c = 0; c < CIN - 1; ++c) {
        // prefetch channel c+1 into registers (overlaps with compute)
        float2 pf[5];
        {
            const float2* cp = reinterpret_cast<const float2*>(nx) + fo2;
            #pragma unroll
            for (int u = 0; u < 5; ++u) {
                int li = tid + u * THR;
                if (u < 4 || li < NT2) pf[u] = __ldg(cp + u * THR);
            }
        }

        compute(smem[par]);

        {
            float4* s4 = reinterpret_cast<float4*>(smem[par ^ 1]);
            #pragma unroll
            for (int u = 0; u < 5; ++u) {
                int li = tid + u * THR;
                if (u < 4 || li < NT2)
                    s4[li] = make_float4(pf[u].x, pf[u].x, pf[u].y, pf[u].y);
            }
        }
        __syncthreads();
        par ^= 1;
        nx += CHP;
        if (LAYER == 1 && c + 2 == 128) nx = inB;   // switch to h1 region
    }
    compute(smem[par]);                  // last channel

    // -------- LSTM gate epilogue ---------------------------------------------
    #pragma unroll
    for (int kk = 0; kk < KPB; ++kk) {
        const int k = k0 + kk;
        #pragma unroll
        for (int r = 0; r < RPT; ++r) {
            int y  = y0 + ty * RPT + r;
            int ci = k * HW + y * Wd + tx;
            float zi, zf, zo, zg;
            unpack2(accIF[kk][r], zi, zf);
            unpack2(accOG[kk][r], zo, zg);
            float cprev = cst[ci];
            float cn = sigf(zf) * cprev + sigf(zi) * tanhf(zg);
            float hn = sigf(zo) * tanhf(cn);
            cst[ci] = cn;
            houtp[k * CHP + (y + 1) * PW + (tx + 1)] = hn;
        }
    }
}

// ---------------- final output copy ------------------------------------------
// h_last of layer1 (padded) -> (B, 12, 4096, 1) contiguous output.
__global__ void copy_out(float* __restrict__ out) {
    int i = blockIdx.x * blockDim.x + threadIdx.x;
    if (i < Bsz * HID1 * HW) {
        int b = i / (HID1 * HW);
        int r = i % (HID1 * HW);
        int k = r >> 12;
        int s = r & 4095;
        int y = s >> 6, x = s & 63;
        out[i] = g_h1p[0][b * (HID1 * CHP) + k * CHP + (y + 1) * PW + (x + 1)];
    }
}

// ============================================================================
extern "C" void kernel_launch(void* const* d_in, const int* in_sizes, int n_in,
                              void* d_out, int out_size) {
    (void)in_sizes; (void)n_in; (void)out_size;
    const float* history = (const float*)d_in[0];   // (16,12,4096,1)
    const float* W0 = (const float*)d_in[2];        // (512,129,3,3)
    const float* b0 = (const float*)d_in[3];        // (512,)
    const float* W1 = (const float*)d_in[4];        // (48,140,3,3)
    const float* b1 = (const float*)d_in[5];        // (48,)
    float* out = (float*)d_out;

    // zero all state (halos stay zero; replay-deterministic)
    {
        long n4 = (long)2 * Bsz * CIN0 * CHP / 4;
        zero_state<<<(unsigned)((n4 + 255) / 256), 256>>>();
    }
    prep_w<0><<<(HID0 * CIN0 * 9 + 255) / 256, 256>>>(W0, b0);
    prep_w<1><<<(HID1 * CIN1 * 9 + 255) / 256, 256>>>(W1, b1);

    for (int t = 0; t < LSEQ; ++t) {
        int p = t & 1;
        pad_x<<<(Bsz * HW + 255) / 256, 256>>>(history, t, p);
        conv_step<0><<<dim3(Hd / Cfg<0>::TILEH, HID0 / Cfg<0>::KPB, Bsz), THR>>>(t, p);
        conv_step<1><<<dim3(Hd / Cfg<1>::TILEH, HID1 / Cfg<1>::KPB, Bsz), THR>>>(t, p);
    }

    // after t=11 (p=1), layer1 wrote h1 into g_h1p[0]
    copy_out<<<(Bsz * HID1 * HW + 255) / 256, 256>>>(out);
}

// round 17
// speedup vs baseline: 1.9209x; 1.0110x over previous
#include <cuda_runtime.h>
#include <cuda_bf16.h>
#include <math.h>

// ============================================================================
// ConvLSTM (2 stacked layers, 12 timesteps) on GB300.
//   Layer0: Cin=129 (1 input + 128 hidden), hid=128
//   Layer1: Cin=140 (128 from layer0 + 12 hidden), hid=12
//   B=16, H=W=64.
// R16: single fused "phase" launch per timestep = conv1(t-1) + conv0(t) +
//      pad_x(t+1) as disjoint block ranges (layer1 blocks first). Layer1
//      re-tiled to KPB=4 x 3 k-groups (ideal FLOPs, no redundant channel
//      streaming). Keeps R11's winning geometry: 128 thr, launch_bounds(128,3)
//      (170-reg budget, no spills), tied fma.rn.f32x2, duplicated-lane smem,
//      padded-halo buffers.
// ============================================================================

#define Bsz  16
#define Hd   64
#define Wd   64
#define HW   4096
#define LSEQ 12

#define HID0 128
#define CIN0 129
#define HID1 12
#define CIN1 140

#define PW   66            // padded row stride
#define CHP  (66*66)       // padded channel size = 4356
#define THR  128           // threads per block

#define L1B  384           // layer1 blocks (8 ytiles x 3 kgroups x 16 b)
#define L0B  4096          // layer0 blocks (4 ytiles x 64 kgroups x 16 b)
#define PXB  128           // pad blocks (65536 / (128 thr * 4))
#define NT0  1188          // layer0 tile float2 entries (18*66) = smem size

typedef unsigned long long u64t;

// ---------------- per-layer tiling config ------------------------------------
template<int LAYER> struct Cfg;
template<> struct Cfg<0> {
    static constexpr int HIDN = 128, CIN = 129;
    static constexpr int KPB = 2, RPT = 8, TILEH = 16, SROWS = 18;
};
template<> struct Cfg<1> {
    static constexpr int HIDN = 12, CIN = 140;
    static constexpr int KPB = 4, RPT = 4, TILEH = 8, SROWS = 10;
};

// ---------------- persistent device state (no runtime allocation) ----------
// g_a0[p]: per batch, 129 padded channel slots: [0]=x_t, [1..128]=h0
__device__ __align__(16) float g_a0[2][Bsz*CIN0*CHP];
__device__ __align__(16) float g_h1p[2][Bsz*HID1*CHP];   // padded h1
__device__ __align__(16) float g_c0[Bsz*HID0*HW];        // unpadded c
__device__ __align__(16) float g_c1[Bsz*HID1*HW];
__device__ float4 g_wp0[HID0*CIN0*9];   // [k][c][tap] -> (wi,wf,wo,wg)
__device__ float4 g_bp0[HID0];
__device__ float4 g_wp1[HID1*CIN1*9];
__device__ float4 g_bp1[HID1];

// ---------------- packed f32x2 helpers --------------------------------------
__device__ __forceinline__ u64t pack2(float a, float b) {
    u64t r;
    asm("mov.b64 %0, {%1, %2};" : "=l"(r) : "f"(a), "f"(b));
    return r;
}
__device__ __forceinline__ void fma2ip(u64t& acc, u64t a, u64t b) {
    asm("fma.rn.f32x2 %0, %1, %2, %0;" : "+l"(acc) : "l"(a), "l"(b));
}
__device__ __forceinline__ void unpack2(u64t v, float& lo, float& hi) {
    asm("mov.b64 {%0, %1}, %2;" : "=f"(lo), "=f"(hi) : "l"(v));
}
__device__ __forceinline__ float sigf(float x) { return 1.0f / (1.0f + expf(-x)); }

// ---------------- weight/bias permutation -----------------------------------
template<int LAYER>
__global__ void prep_w(const float* __restrict__ W, const float* __restrict__ bias) {
    constexpr int HIDN = Cfg<LAYER>::HIDN;
    constexpr int CIN  = Cfg<LAYER>::CIN;
    float4* wp = (LAYER == 0) ? g_wp0 : g_wp1;
    float4* bp = (LAYER == 0) ? g_bp0 : g_bp1;

    int i = blockIdx.x * blockDim.x + threadIdx.x;
    if (i < HIDN * CIN * 9) {
        int tap = i % 9;
        int c   = (i / 9) % CIN;
        int k   = i / (9 * CIN);
        float4 v;
        v.x = W[((0 * HIDN + k) * CIN + c) * 9 + tap];
        v.y = W[((1 * HIDN + k) * CIN + c) * 9 + tap];
        v.z = W[((2 * HIDN + k) * CIN + c) * 9 + tap];
        v.w = W[((3 * HIDN + k) * CIN + c) * 9 + tap];
        wp[i] = v;
    }
    if (i < HIDN) {
        bp[i] = make_float4(bias[0 * HIDN + i], bias[1 * HIDN + i],
                            bias[2 * HIDN + i], bias[3 * HIDN + i]);
    }
}

// ---------------- state zeroing (every launch: deterministic replays) -------
__global__ void zero_state() {
    long i = (long)blockIdx.x * blockDim.x + threadIdx.x;
    float4 z = make_float4(0.f, 0.f, 0.f, 0.f);
    if (i < (long)2 * Bsz * CIN0 * CHP / 4) reinterpret_cast<float4*>(g_a0)[i]  = z;
    if (i < (long)2 * Bsz * HID1 * CHP / 4) reinterpret_cast<float4*>(g_h1p)[i] = z;
    if (i < (long)Bsz * HID0 * HW / 4)      reinterpret_cast<float4*>(g_c0)[i]  = z;
    if (i < (long)Bsz * HID1 * HW / 4)      reinterpret_cast<float4*>(g_c1)[i]  = z;
}

// ---------------- x padding body: write x_t into slot 0 of buffer t&1 --------
__device__ __forceinline__ void pad_body(const float* __restrict__ hist,
                                         int t, int bidx) {
    int i = bidx * (THR * 4) + threadIdx.x * 4;       // 128 blk * 512 = 65536
    int b = i >> 12;
    int r = i & 4095;
    int y = r >> 6, x = r & 63;
    const float4 v = *reinterpret_cast<const float4*>(
        hist + (b * LSEQ + t) * HW + r);
    float* dst = &g_a0[t & 1][b * (CIN0 * CHP) + (y + 1) * PW + (x + 1)];
    dst[0] = v.x; dst[1] = v.y; dst[2] = v.z; dst[3] = v.w;
}

// ---------------- fused conv + LSTM gate body --------------------------------
// Each thread: one x-column, RPT consecutive rows, KPB output channels.
// Activation tiles: duplicated-lane float2 in smem -> one LDS.64 = packed op.
template<int LAYER>
__device__ __forceinline__ void conv_body(int bidx, int t,
                                          float2 (*smem)[NT0]) {
    using C = Cfg<LAYER>;
    constexpr int CIN  = C::CIN;
    constexpr int KPB  = C::KPB;
    constexpr int RPT  = C::RPT;
    constexpr int NTF2 = C::SROWS * PW / 2;                 // tile in float2 units
    constexpr int FILLIT = (NTF2 + THR - 1) / THR;

    int yt, kg, b;
    if (LAYER == 0) { yt = bidx & 3; kg = (bidx >> 2) & 63; b = bidx >> 8; }
    else            { yt = bidx & 7; kg = (bidx >> 3) % 3;  b = bidx / 24; }

    const int p = t & 1;
    const float* inA;
    const float* inB = nullptr;
    float* houtp;     // padded h output, batch base
    float* cst;       // unpadded c, batch base
    const float4* __restrict__ wp;
    const float4* __restrict__ bp;

    if (LAYER == 0) {
        inA   = g_a0[p] + b * (CIN0 * CHP);                 // slots 0..128
        houtp = g_a0[p ^ 1] + b * (CIN0 * CHP) + CHP;       // k -> slot k+1
        cst   = g_c0 + b * (HID0 * HW);
        wp = g_wp0; bp = g_bp0;
    } else {
        inA   = g_a0[p ^ 1] + b * (CIN0 * CHP) + CHP;       // h0(t), 128 ch
        inB   = g_h1p[p] + b * (HID1 * CHP);                // h1(t-1), 12 ch
        houtp = g_h1p[p ^ 1] + b * (HID1 * CHP);
        cst   = g_c1 + b * (HID1 * HW);
        wp = g_wp1; bp = g_bp1;
    }

    const int tid = threadIdx.x;
    const int tx  = tid & 63;
    const int ty  = tid >> 6;            // 0..1
    const int k0  = kg * KPB;
    const int y0  = yt * C::TILEH;
    const int fo2 = (y0 * PW) / 2 + tid; // fill base in float2 units (aligned)

    // accumulators: packed (i,f) and (o,g), init with bias
    u64t accIF[KPB][RPT], accOG[KPB][RPT];
    #pragma unroll
    for (int kk = 0; kk < KPB; ++kk) {
        float4 bk = bp[k0 + kk];
        u64t bif = pack2(bk.x, bk.y);
        u64t bog = pack2(bk.z, bk.w);
        #pragma unroll
        for (int r = 0; r < RPT; ++r) { accIF[kk][r] = bif; accOG[kk][r] = bog; }
    }

    const int base0 = (ty * RPT) * PW + tx;
    const ulonglong2* wrun =
        reinterpret_cast<const ulonglong2*>(wp + (k0 * CIN) * 9);

    auto compute = [&](const float2* sb) {
        const u64t* st = reinterpret_cast<const u64t*>(sb);
        u64t ax[RPT + 2][3];
        #pragma unroll
        for (int i = 0; i < RPT + 2; ++i)
            #pragma unroll
            for (int j = 0; j < 3; ++j)
                ax[i][j] = st[base0 + i * PW + j];
        #pragma unroll
        for (int kk = 0; kk < KPB; ++kk) {
            const ulonglong2* wc = wrun + kk * (CIN * 9);
            #pragma unroll
            for (int d = 0; d < 3; ++d) {
                ulonglong2 w0 = wc[d * 3 + 0];
                ulonglong2 w1 = wc[d * 3 + 1];
                ulonglong2 w2 = wc[d * 3 + 2];
                #pragma unroll
                for (int r = 0; r < RPT; ++r) {
                    const int i = d + r;
                    fma2ip(accIF[kk][r], w0.x, ax[i][0]);
                    fma2ip(accOG[kk][r], w0.y, ax[i][0]);
                    fma2ip(accIF[kk][r], w1.x, ax[i][1]);
                    fma2ip(accOG[kk][r], w1.y, ax[i][1]);
                    fma2ip(accIF[kk][r], w2.x, ax[i][2]);
                    fma2ip(accOG[kk][r], w2.y, ax[i][2]);
                }
            }
        }
        wrun += 9;
    };

    // prologue: fill channel 0 (contiguous float2 spans of padded channel)
    {
        const float2* cp = reinterpret_cast<const float2*>(inA) + fo2;
        float4* s4 = reinterpret_cast<float4*>(smem[0]);
        #pragma unroll
        for (int u = 0; u < FILLIT; ++u) {
            int li = tid + u * THR;
            if (u < FILLIT - 1 || li < NTF2) {
                float2 v = __ldg(cp + u * THR);
                s4[li] = make_float4(v.x, v.x, v.y, v.y);
            }
        }
    }
    __syncthreads();

    const float* nx = inA + CHP;         // next fill channel (ch 1)
    int par = 0;
    for (int c = 0; c < CIN - 1; ++c) {
        // prefetch channel c+1 into registers (overlaps with compute)
        float2 pf[FILLIT];
        {
            const float2* cp = reinterpret_cast<const float2*>(nx) + fo2;
            #pragma unroll
            for (int u = 0; u < FILLIT; ++u) {
                int li = tid + u * THR;
                if (u < FILLIT - 1 || li < NTF2) pf[u] = __ldg(cp + u * THR);
            }
        }

        compute(smem[par]);

        {
            float4* s4 = reinterpret_cast<float4*>(smem[par ^ 1]);
            #pragma unroll
            for (int u = 0; u < FILLIT; ++u) {
                int li = tid + u * THR;
                if (u < FILLIT - 1 || li < NTF2)
                    s4[li] = make_float4(pf[u].x, pf[u].x, pf[u].y, pf[u].y);
            }
        }
        __syncthreads();
        par ^= 1;
        nx += CHP;
        if (LAYER == 1 && c + 2 == 128) nx = inB;   // switch to h1 region
    }
    compute(smem[par]);                  // last channel

    // -------- LSTM gate epilogue ---------------------------------------------
    #pragma unroll
    for (int kk = 0; kk < KPB; ++kk) {
        const int k = k0 + kk;
        #pragma unroll
        for (int r = 0; r < RPT; ++r) {
            int y  = y0 + ty * RPT + r;
            int ci = k * HW + y * Wd + tx;
            float zi, zf, zo, zg;
            unpack2(accIF[kk][r], zi, zf);
            unpack2(accOG[kk][r], zo, zg);
            float cprev = cst[ci];
            float cn = sigf(zf) * cprev + sigf(zi) * tanhf(zg);
            float hn = sigf(zo) * tanhf(cn);
            cst[ci] = cn;
            houtp[k * CHP + (y + 1) * PW + (tx + 1)] = hn;
        }
    }
}

// ---------------- fused per-timestep phase kernel ----------------------------
// One launch per phase t in [-1, 12]:
//   blocks [0, L1B):           conv1(t-1)   (if t >= 1)
//   blocks [L1B, L1B+L0B):     conv0(t)     (if 0 <= t < LSEQ)
//   blocks [L1B+L0B, +PXB):    pad x(t+1)   (if t+1 < LSEQ)
// All three are mutually independent within a phase (disjoint writes,
// consistent read snapshots). Heaviest blocks (layer1) are scheduled first.
__global__ __launch_bounds__(THR, 3)
void phase_step(const float* __restrict__ hist, int t) {
    __shared__ float2 smem[2][NT0];
    const int bx = blockIdx.x;
    if (bx < L1B) {
        if (t >= 1) conv_body<1>(bx, t - 1, smem);
    } else if (bx < L1B + L0B) {
        if (t >= 0 && t < LSEQ) conv_body<0>(bx - L1B, t, smem);
    } else {
        if (t + 1 < LSEQ) pad_body(hist, t + 1, bx - L1B - L0B);
    }
}

// ---------------- final output copy ------------------------------------------
// h_last of layer1 (padded) -> (B, 12, 4096, 1) contiguous output.
__global__ void copy_out(float* __restrict__ out) {
    int i = blockIdx.x * blockDim.x + threadIdx.x;
    if (i < Bsz * HID1 * HW) {
        int b = i / (HID1 * HW);
        int r = i % (HID1 * HW);
        int k = r >> 12;
        int s = r & 4095;
        int y = s >> 6, x = s & 63;
        out[i] = g_h1p[0][b * (HID1 * CHP) + k * CHP + (y + 1) * PW + (x + 1)];
    }
}

// ============================================================================
extern "C" void kernel_launch(void* const* d_in, const int* in_sizes, int n_in,
                              void* d_out, int out_size) {
    (void)in_sizes; (void)n_in; (void)out_size;
    const float* history = (const float*)d_in[0];   // (16,12,4096,1)
    const float* W0 = (const float*)d_in[2];        // (512,129,3,3)
    const float* b0 = (const float*)d_in[3];        // (512,)
    const float* W1 = (const float*)d_in[4];        // (48,140,3,3)
    const float* b1 = (const float*)d_in[5];        // (48,)
    float* out = (float*)d_out;

    // zero all state (halos stay zero; replay-deterministic)
    {
        long n4 = (long)2 * Bsz * CIN0 * CHP / 4;
        zero_state<<<(unsigned)((n4 + 255) / 256), 256>>>();
    }
    prep_w<0><<<(HID0 * CIN0 * 9 + 255) / 256, 256>>>(W0, b0);
    prep_w<1><<<(HID1 * CIN1 * 9 + 255) / 256, 256>>>(W1, b1);

    // phases: t=-1 pads x(0); t=0..11 run conv0(t) [+ conv1(t-1), pad x(t+1)];
    // t=12 drains conv1(11).
    for (int t = -1; t <= LSEQ; ++t) {
        phase_step<<<L1B + L0B + PXB, THR>>>(history, t);
    }

    // layer1 step 11 wrote h1 into g_h1p[0]
    copy_out<<<(Bsz * HID1 * HW + 255) / 256, 256>>>(out);
}